// round 13
// baseline (speedup 1.0000x reference)
#include <cuda_runtime.h>
#include <math.h>
#include <stdint.h>

#define F32_INF __int_as_float(0x7f800000)

// ---------------- problem constants ----------------
#define NB 8
#define NS 512
#define NE 768
#define NGE 32
#define NHD 384
#define NL 4096
#define LAMBDA_INIT 0.2f
#define SCALING 0.05103103630798287f   // 384^-0.5
#define KSPLIT 4

// k-group permutation: within each 8-col group, col c -> (c&3)*2 + (c>>2)
// so thread tg's MMA pair {tg, tg+4} lands at adjacent {2tg, 2tg+1}.
__host__ __device__ __forceinline__ int permc(int c) {
    return (c & ~7) | ((c & 3) << 1) | ((c >> 2) & 1);
}

// ---------------- scratch ----------------
__device__ float g_QI[NB * NS * NE];                    // tf32-rounded, k-permuted query
__device__ float g_KI[NB * NL * NGE];                   // tf32-rounded, k-permuted key
__device__ float g_W1[NE * NE];                         // tf32-rounded Wq (NN, unpermuted)
__device__ float g_W2[NGE * 2 * NE];                    // tf32-rounded Wkv
__device__ float g_W3[NE * NE];                         // tf32-rounded Wout
__device__ float g_Q[NB * NS * NE];                     // Q (tf32, k-permuted)
__device__ float g_K[(size_t)NB * NL * NE];             // K (tf32, k-permuted, ld 768)
__device__ float g_V[(size_t)NB * NL * NE];             // V (tf32, ld 768)
__device__ float g_S[(size_t)NB * 2 * NS * NL];         // raw scores
__device__ float g_P[(size_t)KSPLIT * NB * NS * NE];    // split-K partials for AV
__device__ float g_X[NB * NS * NE];                     // normed (tf32, k-permuted)
__device__ float g_lambda;
__device__ int   g_mask_mode;   // 0=uint8, 1=int32, 2=float32

// ---------------- cp.async helpers ----------------
__device__ __forceinline__ uint32_t smem_u32(const void* p) {
    return (uint32_t)__cvta_generic_to_shared(p);
}
#define CP_ASYNC16(dst, src) \
    asm volatile("cp.async.cg.shared.global [%0], [%1], 16;\n" :: "r"(dst), "l"(src))
#define CP_COMMIT() asm volatile("cp.async.commit_group;\n" ::)
#define CP_WAIT(N)  asm volatile("cp.async.wait_group %0;\n" :: "n"(N))

// ---------------- tf32 helpers ----------------
__device__ __forceinline__ uint32_t to_tf32_u(float x) {
    uint32_t r;
    asm("cvt.rna.tf32.f32 %0, %1;" : "=r"(r) : "f"(x));
    return r;
}
__device__ __forceinline__ float to_tf32_f(float x) {
    return __uint_as_float(to_tf32_u(x));
}
__device__ __forceinline__ void mma_tf32(float* d, const uint32_t* a, const uint32_t* b) {
    asm volatile(
        "mma.sync.aligned.m16n8k8.row.col.f32.tf32.tf32.f32 "
        "{%0,%1,%2,%3}, {%4,%5,%6,%7}, {%8,%9}, {%0,%1,%2,%3};"
        : "+f"(d[0]), "+f"(d[1]), "+f"(d[2]), "+f"(d[3])
        : "r"(a[0]), "r"(a[1]), "r"(a[2]), "r"(a[3]), "r"(b[0]), "r"(b[1]));
}

// ---------------- fused pre-round (5 segments, optional k-permute) ----------------
struct RoundArgs {
    const float* src[5];
    float* dst[5];
    int end4[5];   // cumulative float4 counts
    int perm[5];
};
__global__ void round_all_kernel(RoundArgs a) {
    int i = blockIdx.x * blockDim.x + threadIdx.x;   // float4 index
    if (i >= a.end4[4]) return;
    int seg = 0;
    while (i >= a.end4[seg]) seg++;
    int j = i - (seg ? a.end4[seg - 1] : 0);
    float4 v = reinterpret_cast<const float4*>(a.src[seg])[j];
    v.x = to_tf32_f(v.x); v.y = to_tf32_f(v.y);
    v.z = to_tf32_f(v.z); v.w = to_tf32_f(v.w);
    if (a.perm[seg]) {
        float* d = a.dst[seg];
        int c = j * 4;
        d[permc(c)]     = v.x;
        d[permc(c + 1)] = v.y;
        d[permc(c + 2)] = v.z;
        d[permc(c + 3)] = v.w;
    } else {
        reinterpret_cast<float4*>(a.dst[seg])[j] = v;
    }
}

// ---------------- mask dtype detection ----------------
__global__ void detect_mask_kernel(const unsigned char* __restrict__ km) {
    __shared__ int s_non01, s_nonmult4;
    if (threadIdx.x == 0) { s_non01 = 0; s_nonmult4 = 0; }
    __syncthreads();
    int non01 = 0, nm4 = 0;
    for (int i = threadIdx.x; i < 32768; i += 256) {
        unsigned char v = km[i];
        if (v > 1) non01 = 1;
        if (v != 0 && (i & 3) != 0) nm4 = 1;
    }
    if (non01) atomicOr(&s_non01, 1);
    if (nm4)   atomicOr(&s_nonmult4, 1);
    __syncthreads();
    if (threadIdx.x == 0)
        g_mask_mode = s_non01 ? 2 : (s_nonmult4 ? 0 : 1);
}

__device__ __forceinline__ bool mask_at(const void* p, long idx, int mode) {
    if (mode == 1) return ((const int*)p)[idx] != 0;
    if (mode == 2) return ((const float*)p)[idx] != 0.0f;
    return ((const unsigned char*)p)[idx] != 0;
}

// ---------------- lambda scalar ----------------
__global__ void lambda_kernel(const float* __restrict__ lq1, const float* __restrict__ lk1,
                              const float* __restrict__ lq2, const float* __restrict__ lk2) {
    __shared__ float red1[12], red2[12];
    int t = threadIdx.x;
    float a = lq1[t] * lk1[t];
    float b = lq2[t] * lk2[t];
    #pragma unroll
    for (int o = 16; o > 0; o >>= 1) {
        a += __shfl_xor_sync(0xFFFFFFFFu, a, o);
        b += __shfl_xor_sync(0xFFFFFFFFu, b, o);
    }
    if ((t & 31) == 0) { red1[t >> 5] = a; red2[t >> 5] = b; }
    __syncthreads();
    if (t == 0) {
        float s1 = 0.f, s2 = 0.f;
        for (int i = 0; i < 12; i++) { s1 += red1[i]; s2 += red2[i]; }
        g_lambda = expf(s1) - expf(s2) + LAMBDA_INIT;
    }
}

// ---------------- tf32 GEMM, 3-stage cp.async ring ----------------
// C[M,N] = alpha * A[M,K] @ (TB ? B[N,K]^T : B[K,N])
// PERM: A stored k-permuted (float2 fragment loads); if TB also B k-permuted.
// CVTA: round A in-loop (A is exact fp32, e.g. diff).
// OMODE 0: fp32 raw C. OMODE 1: tf32 + k-permuted C (Q). OMODE 2: KV split (K permuted | V plain).
template <bool TB, int OMODE, bool CVTA, bool PERM>
__global__ __launch_bounds__(256) void mma_gemm(
    const float* __restrict__ A, const float* __restrict__ B,
    float* __restrict__ C, float* __restrict__ C2,
    int M, int N, int K, int lda, int ldb, int ldc, float alpha, int dv,
    long sAhi, long sAlo, long sBhi, long sBlo, long sChi, long sClo) {
    const int BM = 128, BN = 128, BK = 16;
    const int APITCH = BK + 4;
    const int BPITCH_NT = BK + 4;
    const int BPITCH_NN = BN + 8;
    const int BSTG = TB ? BN * BPITCH_NT : BK * BPITCH_NN;
    __shared__ __align__(16) float As[3][BM * APITCH];
    __shared__ __align__(16) float Bs[3][BSTG];

    int z = blockIdx.z;
    A += (long)(z / dv) * sAhi + (long)(z % dv) * sAlo;
    B += (long)(z / dv) * sBhi + (long)(z % dv) * sBlo;
    long coff = (long)(z / dv) * sChi + (long)(z % dv) * sClo;

    int m0 = blockIdx.y * BM, n0 = blockIdx.x * BN;
    int tid = threadIdx.x;
    int warp = tid >> 5, lane = tid & 31;
    int g = lane >> 2, tg = lane & 3;
    int wm = (warp & 3) * 32, wn = (warp >> 2) * 64;

    int ar[2], ac[2], br[2], bc[2];
    #pragma unroll
    for (int rep = 0; rep < 2; rep++) {
        int idx = rep * 256 + tid;
        ar[rep] = idx >> 2; ac[rep] = (idx & 3) * 4;
        if (TB) { br[rep] = idx >> 2; bc[rep] = (idx & 3) * 4; }
        else    { br[rep] = idx >> 5; bc[rep] = (idx & 31) * 4; }
    }

    int niter = K / BK;

    auto prefetch = [&](int st, int buf) {
        int k0 = st * BK;
        #pragma unroll
        for (int rep = 0; rep < 2; rep++) {
            CP_ASYNC16(smem_u32(&As[buf][ar[rep] * APITCH + ac[rep]]),
                       &A[(long)(m0 + ar[rep]) * lda + k0 + ac[rep]]);
            if (TB)
                CP_ASYNC16(smem_u32(&Bs[buf][br[rep] * BPITCH_NT + bc[rep]]),
                           &B[(long)(n0 + br[rep]) * ldb + k0 + bc[rep]]);
            else
                CP_ASYNC16(smem_u32(&Bs[buf][br[rep] * BPITCH_NN + bc[rep]]),
                           &B[(long)(k0 + br[rep]) * ldb + n0 + bc[rep]]);
        }
    };

    prefetch(0, 0); CP_COMMIT();
    prefetch(1, 1); CP_COMMIT();

    float acc[2][8][4] = {};

    for (int it = 0; it < niter; it++) {
        int cur = it % 3;
        CP_WAIT(1);
        __syncthreads();

        if (it + 2 < niter) prefetch(it + 2, (it + 2) % 3);
        CP_COMMIT();

        const float* Asc = As[cur];
        const float* Bsc = Bs[cur];
        #pragma unroll
        for (int kk = 0; kk < BK; kk += 8) {
            uint32_t af[2][4], bf[8][2];
            #pragma unroll
            for (int m = 0; m < 2; m++) {
                int row = wm + m * 16;
                if (PERM) {
                    float2 v0 = *reinterpret_cast<const float2*>(&Asc[(row + g)     * APITCH + kk + 2 * tg]);
                    float2 v1 = *reinterpret_cast<const float2*>(&Asc[(row + g + 8) * APITCH + kk + 2 * tg]);
                    af[m][0] = __float_as_uint(v0.x); af[m][2] = __float_as_uint(v0.y);
                    af[m][1] = __float_as_uint(v1.x); af[m][3] = __float_as_uint(v1.y);
                } else if (CVTA) {
                    af[m][0] = to_tf32_u(Asc[(row + g)     * APITCH + kk + tg]);
                    af[m][1] = to_tf32_u(Asc[(row + g + 8) * APITCH + kk + tg]);
                    af[m][2] = to_tf32_u(Asc[(row + g)     * APITCH + kk + tg + 4]);
                    af[m][3] = to_tf32_u(Asc[(row + g + 8) * APITCH + kk + tg + 4]);
                } else {
                    af[m][0] = __float_as_uint(Asc[(row + g)     * APITCH + kk + tg]);
                    af[m][1] = __float_as_uint(Asc[(row + g + 8) * APITCH + kk + tg]);
                    af[m][2] = __float_as_uint(Asc[(row + g)     * APITCH + kk + tg + 4]);
                    af[m][3] = __float_as_uint(Asc[(row + g + 8) * APITCH + kk + tg + 4]);
                }
            }
            #pragma unroll
            for (int n = 0; n < 8; n++) {
                int col = wn + n * 8 + g;
                if (TB) {
                    if (PERM) {
                        float2 v = *reinterpret_cast<const float2*>(&Bsc[col * BPITCH_NT + kk + 2 * tg]);
                        bf[n][0] = __float_as_uint(v.x); bf[n][1] = __float_as_uint(v.y);
                    } else {
                        bf[n][0] = __float_as_uint(Bsc[col * BPITCH_NT + kk + tg]);
                        bf[n][1] = __float_as_uint(Bsc[col * BPITCH_NT + kk + tg + 4]);
                    }
                } else {
                    bf[n][0] = __float_as_uint(Bsc[(kk + tg)     * BPITCH_NN + col]);
                    bf[n][1] = __float_as_uint(Bsc[(kk + tg + 4) * BPITCH_NN + col]);
                }
            }
            #pragma unroll
            for (int m = 0; m < 2; m++)
                #pragma unroll
                for (int n = 0; n < 8; n++)
                    mma_tf32(acc[m][n], af[m], bf[n]);
        }
    }

    // ---- epilogue ----
    #pragma unroll
    for (int m = 0; m < 2; m++) {
        #pragma unroll
        for (int n = 0; n < 8; n++) {
            int row = m0 + wm + m * 16 + g;
            int col = n0 + wn + n * 8 + tg * 2;
            float v00 = alpha * acc[m][n][0], v01 = alpha * acc[m][n][1];
            float v10 = alpha * acc[m][n][2], v11 = alpha * acc[m][n][3];
            if (OMODE == 0) {
                *reinterpret_cast<float2*>(&C[coff + (long)row * ldc + col]) = make_float2(v00, v01);
                *reinterpret_cast<float2*>(&C[coff + (long)(row + 8) * ldc + col]) = make_float2(v10, v11);
            } else if (OMODE == 1) {
                // tf32-rounded + k-permuted Q
                int c0 = permc(col), c1 = permc(col + 1);
                C[coff + (long)row * ldc + c0] = to_tf32_f(v00);
                C[coff + (long)row * ldc + c1] = to_tf32_f(v01);
                C[coff + (long)(row + 8) * ldc + c0] = to_tf32_f(v10);
                C[coff + (long)(row + 8) * ldc + c1] = to_tf32_f(v11);
            } else {
                if (col < NE) {   // K half: tf32 + permuted
                    int c0 = permc(col), c1 = permc(col + 1);
                    C[(long)row * NE + c0] = to_tf32_f(v00);
                    C[(long)row * NE + c1] = to_tf32_f(v01);
                    C[(long)(row + 8) * NE + c0] = to_tf32_f(v10);
                    C[(long)(row + 8) * NE + c1] = to_tf32_f(v11);
                } else {          // V half: tf32, plain layout
                    *reinterpret_cast<float2*>(&C2[(long)row * NE + col - NE]) =
                        make_float2(to_tf32_f(v00), to_tf32_f(v01));
                    *reinterpret_cast<float2*>(&C2[(long)(row + 8) * NE + col - NE]) =
                        make_float2(to_tf32_f(v10), to_tf32_f(v11));
                }
            }
        }
    }
}

// ---------------- block reductions ----------------
__device__ __forceinline__ float blockReduceMax(float v, float* red) {
    #pragma unroll
    for (int o = 16; o > 0; o >>= 1) v = fmaxf(v, __shfl_xor_sync(0xFFFFFFFFu, v, o));
    int w = threadIdx.x >> 5, lane = threadIdx.x & 31;
    __syncthreads();
    if (lane == 0) red[w] = v;
    __syncthreads();
    v = (lane < (blockDim.x >> 5)) ? red[lane] : -F32_INF;
    #pragma unroll
    for (int o = 16; o > 0; o >>= 1) v = fmaxf(v, __shfl_xor_sync(0xFFFFFFFFu, v, o));
    return v;
}
__device__ __forceinline__ float blockReduceMin(float v, float* red) {
    #pragma unroll
    for (int o = 16; o > 0; o >>= 1) v = fminf(v, __shfl_xor_sync(0xFFFFFFFFu, v, o));
    int w = threadIdx.x >> 5, lane = threadIdx.x & 31;
    __syncthreads();
    if (lane == 0) red[w] = v;
    __syncthreads();
    v = (lane < (blockDim.x >> 5)) ? red[lane] : F32_INF;
    #pragma unroll
    for (int o = 16; o > 0; o >>= 1) v = fminf(v, __shfl_xor_sync(0xFFFFFFFFu, v, o));
    return v;
}
__device__ __forceinline__ float blockReduceSum(float v, float* red) {
    #pragma unroll
    for (int o = 16; o > 0; o >>= 1) v += __shfl_xor_sync(0xFFFFFFFFu, v, o);
    int w = threadIdx.x >> 5, lane = threadIdx.x & 31;
    __syncthreads();
    if (lane == 0) red[w] = v;
    __syncthreads();
    v = (lane < (blockDim.x >> 5)) ? red[lane] : 0.f;
    #pragma unroll
    for (int o = 16; o > 0; o >>= 1) v += __shfl_xor_sync(0xFFFFFFFFu, v, o);
    return v;
}

// ---------------- softmax + differential + min-shift (float4 I/O) ----------------
__global__ __launch_bounds__(256) void softmax_diff_kernel(
    const void* __restrict__ qmask, const void* __restrict__ kmask,
    float* __restrict__ out_diff) {
    __shared__ float p1[NL];
    __shared__ float p2[NL];
    __shared__ float red[32];

    int bs = blockIdx.x;
    int b = bs >> 9;
    int s = bs & 511;
    int tid = threadIdx.x;
    int mode = g_mask_mode;

    bool qm = mask_at(qmask, bs, mode);
    const float* s1 = g_S + ((long)(b * 2 + 0) * NS + s) * NL;
    const float* s2 = g_S + ((long)(b * 2 + 1) * NS + s) * NL;
    long kmbase = (long)b * NL;

    float m1 = -F32_INF, m2 = -F32_INF;
    for (int l0 = tid * 4; l0 < NL; l0 += 1024) {
        float4 a = *reinterpret_cast<const float4*>(s1 + l0);
        float4 c = *reinterpret_cast<const float4*>(s2 + l0);
        float va[4] = {a.x, a.y, a.z, a.w};
        float vc[4] = {c.x, c.y, c.z, c.w};
        #pragma unroll
        for (int j = 0; j < 4; j++) {
            bool mk = qm && mask_at(kmask, kmbase + l0 + j, mode);
            va[j] = mk ? va[j] : -1e20f;
            vc[j] = mk ? vc[j] : -1e20f;
            m1 = fmaxf(m1, va[j]); m2 = fmaxf(m2, vc[j]);
        }
        *reinterpret_cast<float4*>(p1 + l0) = make_float4(va[0], va[1], va[2], va[3]);
        *reinterpret_cast<float4*>(p2 + l0) = make_float4(vc[0], vc[1], vc[2], vc[3]);
    }
    m1 = blockReduceMax(m1, red);
    m2 = blockReduceMax(m2, red);

    float sum1 = 0.f, sum2 = 0.f;
    for (int l = tid; l < NL; l += 256) {
        float e1 = expf(p1[l] - m1);
        float e2 = expf(p2[l] - m2);
        p1[l] = e1; p2[l] = e2;
        sum1 += e1; sum2 += e2;
    }
    sum1 = blockReduceSum(sum1, red);
    sum2 = blockReduceSum(sum2, red);
    float inv1 = 1.f / (sum1 + 1e-8f);
    float inv2 = 1.f / (sum2 + 1e-8f);
    float lam = g_lambda;

    float mn = F32_INF;
    for (int l = tid; l < NL; l += 256) {
        float d = p1[l] * inv1 - lam * (p2[l] * inv2);
        p1[l] = d;
        mn = fminf(mn, d);
    }
    mn = blockReduceMin(mn, red);

    float* od = out_diff + (long)bs * NL;
    for (int l0 = tid * 4; l0 < NL; l0 += 1024) {
        float v[4];
        #pragma unroll
        for (int j = 0; j < 4; j++) {
            bool mk = qm && mask_at(kmask, kmbase + l0 + j, mode);
            v[j] = mk ? (p1[l0 + j] - mn + 1e-20f) : 0.f;
        }
        *reinterpret_cast<float4*>(od + l0) = make_float4(v[0], v[1], v[2], v[3]);
    }
}

// ---------------- split-K reduce + RMS norm (fused), writes tf32 + k-permuted X ----------------
__global__ __launch_bounds__(256) void rmsnorm_kernel(const float* __restrict__ ln) {
    __shared__ float red[32];
    __shared__ float row_buf[NE];
    int row = blockIdx.x;
    int tid = threadIdx.x;
    const long rbase = (long)row * NE;
    const long pstride = (long)NB * NS * NE;
    float ss = 0.f;
    for (int e = tid; e < NE; e += 256) {
        float v = g_P[rbase + e] + g_P[pstride + rbase + e]
                + g_P[2 * pstride + rbase + e] + g_P[3 * pstride + rbase + e];
        row_buf[e] = v;
        ss += v * v;
    }
    ss = blockReduceSum(ss, red);
    float scale = rsqrtf(ss / (float)NE + 1e-5f) * (1.0f - LAMBDA_INIT);
    float* x = g_X + rbase;
    for (int e = tid; e < NE; e += 256)
        x[permc(e)] = to_tf32_f(row_buf[e] * scale * ln[e]);
}

// ---------------- launch ----------------
extern "C" void kernel_launch(void* const* d_in, const int* in_sizes, int n_in,
                              void* d_out, int out_size) {
    const float* query = (const float*)d_in[0];   // (8,512,768)
    const float* key   = (const float*)d_in[1];   // (8,64,64,32)
    const void*  qmask = d_in[2];                 // (8,512)
    const void*  kmask = d_in[3];                 // (8,64,64)
    const float* Wq   = (const float*)d_in[4];
    const float* Wkv  = (const float*)d_in[5];
    const float* Wout = (const float*)d_in[6];
    const float* lq1  = (const float*)d_in[7];
    const float* lk1  = (const float*)d_in[8];
    const float* lq2  = (const float*)d_in[9];
    const float* lk2  = (const float*)d_in[10];
    const float* ln   = (const float*)d_in[11];

    float* outp = (float*)d_out;                       // (8,512,768)
    float* diffp = outp + (long)NB * NS * NE;          // (8,512,64,64)

    float *pQI, *pKI, *pW1, *pW2, *pW3, *pQ, *pK, *pV, *pS, *pP, *pX;
    cudaGetSymbolAddress((void**)&pQI, g_QI);
    cudaGetSymbolAddress((void**)&pKI, g_KI);
    cudaGetSymbolAddress((void**)&pW1, g_W1);
    cudaGetSymbolAddress((void**)&pW2, g_W2);
    cudaGetSymbolAddress((void**)&pW3, g_W3);
    cudaGetSymbolAddress((void**)&pQ,  g_Q);
    cudaGetSymbolAddress((void**)&pK,  g_K);
    cudaGetSymbolAddress((void**)&pV,  g_V);
    cudaGetSymbolAddress((void**)&pS,  g_S);
    cudaGetSymbolAddress((void**)&pP,  g_P);
    cudaGetSymbolAddress((void**)&pX,  g_X);

    detect_mask_kernel<<<1, 256>>>((const unsigned char*)kmask);
    lambda_kernel<<<1, 384>>>(lq1, lk1, lq2, lk2);

    // fused pre-round: query(perm), key(perm), Wq, Wkv, Wout
    {
        RoundArgs ra;
        int n4[5] = { NB * NS * NE / 4, NB * NL * NGE / 4,
                      NE * NE / 4, NGE * 2 * NE / 4, NE * NE / 4 };
        ra.src[0] = query; ra.dst[0] = pQI; ra.perm[0] = 1;
        ra.src[1] = key;   ra.dst[1] = pKI; ra.perm[1] = 1;
        ra.src[2] = Wq;    ra.dst[2] = pW1; ra.perm[2] = 0;
        ra.src[3] = Wkv;   ra.dst[3] = pW2; ra.perm[3] = 0;
        ra.src[4] = Wout;  ra.dst[4] = pW3; ra.perm[4] = 0;
        int acc = 0;
        for (int i = 0; i < 5; i++) { acc += n4[i]; ra.end4[i] = acc; }
        round_all_kernel<<<(acc + 255) / 256, 256>>>(ra);
    }

    // Q = queryR @ WqR -> tf32 + permuted : M=4096, N=768, K=768
    mma_gemm<false, 1, false, true><<<dim3(NE / 128, (NB * NS) / 128, 1), 256>>>(
        pQI, pW1, pQ, nullptr, NB * NS, NE, NE, NE, NE, NE, 1.0f,
        1, 0, 0, 0, 0, 0, 0);

    // KV = keyR @ WkvR -> K(permuted) | V : M=32768, N=1536, K=32
    mma_gemm<false, 2, false, true><<<dim3((2 * NE) / 128, (NB * NL) / 128, 1), 256>>>(
        pKI, pW2, pK, pV, NB * NL, 2 * NE, NGE, NGE, 2 * NE, NE, 1.0f,
        1, 0, 0, 0, 0, 0, 0);

    // scores = SCALING * Qh @ Kh^T (both permuted) : M=512, N=4096, K=384, 16 batches
    mma_gemm<true, 0, false, true><<<dim3(NL / 128, NS / 128, NB * 2), 256>>>(
        pQ, pK, pS, nullptr, NS, NL, NHD, NE, NE, NL, SCALING,
        2,
        (long)NS * NE, (long)NHD,
        (long)NL * NE, (long)NHD,
        (long)2 * NS * NL, (long)NS * NL);

    // softmax + diff + min-shift -> d_out diff region
    softmax_diff_kernel<<<NB * NS, 256>>>(qmask, kmask, diffp);

    // attn_out partials: A=diff (exact fp32, cvt in-loop), B=V
    mma_gemm<false, 0, true, false><<<dim3(NE / 128, NS / 128, NB * KSPLIT), 256>>>(
        diffp, pV, pP, nullptr, NS, NE, NL / KSPLIT, NL, NE, NE, 1.0f,
        KSPLIT,
        (long)NS * NL, (long)(NL / KSPLIT),
        (long)NL * NE, (long)(NL / KSPLIT) * NE,
        (long)NS * NE, (long)NB * NS * NE);

    // split-K reduce + RMS norm (writes tf32 + permuted X)
    rmsnorm_kernel<<<NB * NS, 256>>>(ln);

    // out = XR @ WoutR : M=4096, N=768, K=768
    mma_gemm<false, 0, false, true><<<dim3(NE / 128, (NB * NS) / 128, 1), 256>>>(
        pX, pW3, outp, nullptr, NB * NS, NE, NE, NE, NE, NE, 1.0f,
        1, 0, 0, 0, 0, 0, 0);
}

// round 15
// speedup vs baseline: 1.0688x; 1.0688x over previous
#include <cuda_runtime.h>
#include <math.h>
#include <stdint.h>

#define F32_INF __int_as_float(0x7f800000)

// ---------------- problem constants ----------------
#define NB 8
#define NS 512
#define NE 768
#define NGE 32
#define NHD 384
#define NL 4096
#define LAMBDA_INIT 0.2f
#define SCALING 0.05103103630798287f   // 384^-0.5
#define KSPLIT 4

// k-group permutation: within each 8-col group, col c -> (c&3)*2 + (c>>2)
// so thread tg's MMA pair {tg, tg+4} lands at adjacent {2tg, 2tg+1}.
__host__ __device__ __forceinline__ int permc(int c) {
    return (c & ~7) | ((c & 3) << 1) | ((c >> 2) & 1);
}

// ---------------- scratch ----------------
__device__ float g_QI[NB * NS * NE];                    // tf32-rounded, k-permuted query
__device__ float g_KI[NB * NL * NGE];                   // tf32-rounded, k-permuted key
__device__ float g_W1[NE * NE];                         // tf32-rounded Wq (NN, unpermuted)
__device__ float g_W2[NGE * 2 * NE];                    // tf32-rounded Wkv
__device__ float g_W3[NE * NE];                         // tf32-rounded Wout
__device__ float g_Q[NB * NS * NE];                     // Q (tf32, k-permuted)
__device__ float g_K[(size_t)NB * NL * NE];             // K (tf32, k-permuted, ld 768)
__device__ float g_V[(size_t)NB * NL * NE];             // V (tf32, ld 768)
__device__ float g_S[(size_t)NB * 2 * NS * NL];         // raw scores
__device__ float g_P[(size_t)KSPLIT * NB * NS * NE];    // split-K partials for AV
__device__ float g_X[NB * NS * NE];                     // normed (tf32, k-permuted)
__device__ float g_lambda;
__device__ int   g_mask_mode;   // 0=uint8, 1=int32, 2=float32

// ---------------- cp.async helpers ----------------
__device__ __forceinline__ uint32_t smem_u32(const void* p) {
    return (uint32_t)__cvta_generic_to_shared(p);
}
#define CP_ASYNC16(dst, src) \
    asm volatile("cp.async.cg.shared.global [%0], [%1], 16;\n" :: "r"(dst), "l"(src))
#define CP_COMMIT() asm volatile("cp.async.commit_group;\n" ::)
#define CP_WAIT(N)  asm volatile("cp.async.wait_group %0;\n" :: "n"(N))

// ---------------- tf32 helpers ----------------
__device__ __forceinline__ uint32_t to_tf32_u(float x) {
    uint32_t r;
    asm("cvt.rna.tf32.f32 %0, %1;" : "=r"(r) : "f"(x));
    return r;
}
__device__ __forceinline__ float to_tf32_f(float x) {
    return __uint_as_float(to_tf32_u(x));
}
__device__ __forceinline__ void mma_tf32(float* d, const uint32_t* a, const uint32_t* b) {
    asm volatile(
        "mma.sync.aligned.m16n8k8.row.col.f32.tf32.tf32.f32 "
        "{%0,%1,%2,%3}, {%4,%5,%6,%7}, {%8,%9}, {%0,%1,%2,%3};"
        : "+f"(d[0]), "+f"(d[1]), "+f"(d[2]), "+f"(d[3])
        : "r"(a[0]), "r"(a[1]), "r"(a[2]), "r"(a[3]), "r"(b[0]), "r"(b[1]));
}

// ---------------- fused pre-round (5 segments, optional k-permute) ----------------
struct RoundArgs {
    const float* src[5];
    float* dst[5];
    int end4[5];   // cumulative float4 counts
    int perm[5];
};
__global__ void round_all_kernel(RoundArgs a) {
    int i = blockIdx.x * blockDim.x + threadIdx.x;   // float4 index
    if (i >= a.end4[4]) return;
    int seg = 0;
    while (i >= a.end4[seg]) seg++;
    int j = i - (seg ? a.end4[seg - 1] : 0);
    float4 v = reinterpret_cast<const float4*>(a.src[seg])[j];
    v.x = to_tf32_f(v.x); v.y = to_tf32_f(v.y);
    v.z = to_tf32_f(v.z); v.w = to_tf32_f(v.w);
    if (a.perm[seg]) {
        float* d = a.dst[seg];
        int c = j * 4;
        d[permc(c)]     = v.x;
        d[permc(c + 1)] = v.y;
        d[permc(c + 2)] = v.z;
        d[permc(c + 3)] = v.w;
    } else {
        reinterpret_cast<float4*>(a.dst[seg])[j] = v;
    }
}

// ---------------- mask dtype detection ----------------
__global__ void detect_mask_kernel(const unsigned char* __restrict__ km) {
    __shared__ int s_non01, s_nonmult4;
    if (threadIdx.x == 0) { s_non01 = 0; s_nonmult4 = 0; }
    __syncthreads();
    int non01 = 0, nm4 = 0;
    for (int i = threadIdx.x; i < 32768; i += 256) {
        unsigned char v = km[i];
        if (v > 1) non01 = 1;
        if (v != 0 && (i & 3) != 0) nm4 = 1;
    }
    if (non01) atomicOr(&s_non01, 1);
    if (nm4)   atomicOr(&s_nonmult4, 1);
    __syncthreads();
    if (threadIdx.x == 0)
        g_mask_mode = s_non01 ? 2 : (s_nonmult4 ? 0 : 1);
}

__device__ __forceinline__ bool mask_at(const void* p, long idx, int mode) {
    if (mode == 1) return ((const int*)p)[idx] != 0;
    if (mode == 2) return ((const float*)p)[idx] != 0.0f;
    return ((const unsigned char*)p)[idx] != 0;
}

// ---------------- lambda scalar ----------------
__global__ void lambda_kernel(const float* __restrict__ lq1, const float* __restrict__ lk1,
                              const float* __restrict__ lq2, const float* __restrict__ lk2) {
    __shared__ float red1[12], red2[12];
    int t = threadIdx.x;
    float a = lq1[t] * lk1[t];
    float b = lq2[t] * lk2[t];
    #pragma unroll
    for (int o = 16; o > 0; o >>= 1) {
        a += __shfl_xor_sync(0xFFFFFFFFu, a, o);
        b += __shfl_xor_sync(0xFFFFFFFFu, b, o);
    }
    if ((t & 31) == 0) { red1[t >> 5] = a; red2[t >> 5] = b; }
    __syncthreads();
    if (t == 0) {
        float s1 = 0.f, s2 = 0.f;
        for (int i = 0; i < 12; i++) { s1 += red1[i]; s2 += red2[i]; }
        g_lambda = expf(s1) - expf(s2) + LAMBDA_INIT;
    }
}

// ---------------- tf32 GEMM, 3-stage cp.async ring ----------------
// C[M,N] = alpha * A[M,K] @ (TB ? B[N,K]^T : B[K,N])
// PERM: A stored k-permuted (float2 fragment loads); if TB also B k-permuted.
//       pitch 24 for PERM (conflict-free float2: banks (g*24+2tg) cover each phase),
//       pitch 20 for scalar loads (banks g*20+tg distinct).
// CVTA: round A in-loop (A is exact fp32, e.g. diff).
// OMODE 0: fp32 raw C. OMODE 1: tf32 + k-permuted C (Q). OMODE 2: KV split (K permuted | V plain).
template <bool TB, int OMODE, bool CVTA, bool PERM>
__global__ __launch_bounds__(256) void mma_gemm(
    const float* __restrict__ A, const float* __restrict__ B,
    float* __restrict__ C, float* __restrict__ C2,
    int M, int N, int K, int lda, int ldb, int ldc, float alpha, int dv,
    long sAhi, long sAlo, long sBhi, long sBlo, long sChi, long sClo) {
    const int BM = 128, BN = 128, BK = 16;
    const int APITCH = PERM ? (BK + 8) : (BK + 4);       // 24 : 20
    const int BPITCH_NT = PERM ? (BK + 8) : (BK + 4);
    const int BPITCH_NN = BN + 8;                        // 136
    const int BSTG = TB ? BN * BPITCH_NT : BK * BPITCH_NN;
    __shared__ __align__(16) float As[3][BM * APITCH];
    __shared__ __align__(16) float Bs[3][BSTG];

    int z = blockIdx.z;
    A += (long)(z / dv) * sAhi + (long)(z % dv) * sAlo;
    B += (long)(z / dv) * sBhi + (long)(z % dv) * sBlo;
    long coff = (long)(z / dv) * sChi + (long)(z % dv) * sClo;

    int m0 = blockIdx.y * BM, n0 = blockIdx.x * BN;
    int tid = threadIdx.x;
    int warp = tid >> 5, lane = tid & 31;
    int g = lane >> 2, tg = lane & 3;
    int wm = (warp & 3) * 32, wn = (warp >> 2) * 64;

    int ar[2], ac[2], br[2], bc[2];
    #pragma unroll
    for (int rep = 0; rep < 2; rep++) {
        int idx = rep * 256 + tid;
        ar[rep] = idx >> 2; ac[rep] = (idx & 3) * 4;
        if (TB) { br[rep] = idx >> 2; bc[rep] = (idx & 3) * 4; }
        else    { br[rep] = idx >> 5; bc[rep] = (idx & 31) * 4; }
    }

    int niter = K / BK;

    auto prefetch = [&](int st, int buf) {
        int k0 = st * BK;
        #pragma unroll
        for (int rep = 0; rep < 2; rep++) {
            CP_ASYNC16(smem_u32(&As[buf][ar[rep] * APITCH + ac[rep]]),
                       &A[(long)(m0 + ar[rep]) * lda + k0 + ac[rep]]);
            if (TB)
                CP_ASYNC16(smem_u32(&Bs[buf][br[rep] * BPITCH_NT + bc[rep]]),
                           &B[(long)(n0 + br[rep]) * ldb + k0 + bc[rep]]);
            else
                CP_ASYNC16(smem_u32(&Bs[buf][br[rep] * BPITCH_NN + bc[rep]]),
                           &B[(long)(k0 + br[rep]) * ldb + n0 + bc[rep]]);
        }
    };

    prefetch(0, 0); CP_COMMIT();
    prefetch(1, 1); CP_COMMIT();

    float acc[2][8][4] = {};

    for (int it = 0; it < niter; it++) {
        int cur = it % 3;
        CP_WAIT(1);
        __syncthreads();

        if (it + 2 < niter) prefetch(it + 2, (it + 2) % 3);
        CP_COMMIT();

        const float* Asc = As[cur];
        const float* Bsc = Bs[cur];
        #pragma unroll
        for (int kk = 0; kk < BK; kk += 8) {
            uint32_t af[2][4], bf[8][2];
            #pragma unroll
            for (int m = 0; m < 2; m++) {
                int row = wm + m * 16;
                if (PERM) {
                    float2 v0 = *reinterpret_cast<const float2*>(&Asc[(row + g)     * APITCH + kk + 2 * tg]);
                    float2 v1 = *reinterpret_cast<const float2*>(&Asc[(row + g + 8) * APITCH + kk + 2 * tg]);
                    af[m][0] = __float_as_uint(v0.x); af[m][2] = __float_as_uint(v0.y);
                    af[m][1] = __float_as_uint(v1.x); af[m][3] = __float_as_uint(v1.y);
                } else if (CVTA) {
                    af[m][0] = to_tf32_u(Asc[(row + g)     * APITCH + kk + tg]);
                    af[m][1] = to_tf32_u(Asc[(row + g + 8) * APITCH + kk + tg]);
                    af[m][2] = to_tf32_u(Asc[(row + g)     * APITCH + kk + tg + 4]);
                    af[m][3] = to_tf32_u(Asc[(row + g + 8) * APITCH + kk + tg + 4]);
                } else {
                    af[m][0] = __float_as_uint(Asc[(row + g)     * APITCH + kk + tg]);
                    af[m][1] = __float_as_uint(Asc[(row + g + 8) * APITCH + kk + tg]);
                    af[m][2] = __float_as_uint(Asc[(row + g)     * APITCH + kk + tg + 4]);
                    af[m][3] = __float_as_uint(Asc[(row + g + 8) * APITCH + kk + tg + 4]);
                }
            }
            #pragma unroll
            for (int n = 0; n < 8; n++) {
                int col = wn + n * 8 + g;
                if (TB) {
                    if (PERM) {
                        float2 v = *reinterpret_cast<const float2*>(&Bsc[col * BPITCH_NT + kk + 2 * tg]);
                        bf[n][0] = __float_as_uint(v.x); bf[n][1] = __float_as_uint(v.y);
                    } else {
                        bf[n][0] = __float_as_uint(Bsc[col * BPITCH_NT + kk + tg]);
                        bf[n][1] = __float_as_uint(Bsc[col * BPITCH_NT + kk + tg + 4]);
                    }
                } else {
                    bf[n][0] = __float_as_uint(Bsc[(kk + tg)     * BPITCH_NN + col]);
                    bf[n][1] = __float_as_uint(Bsc[(kk + tg + 4) * BPITCH_NN + col]);
                }
            }
            #pragma unroll
            for (int m = 0; m < 2; m++)
                #pragma unroll
                for (int n = 0; n < 8; n++)
                    mma_tf32(acc[m][n], af[m], bf[n]);
        }
    }

    // ---- epilogue ----
    #pragma unroll
    for (int m = 0; m < 2; m++) {
        #pragma unroll
        for (int n = 0; n < 8; n++) {
            int row = m0 + wm + m * 16 + g;
            int col = n0 + wn + n * 8 + tg * 2;
            float v00 = alpha * acc[m][n][0], v01 = alpha * acc[m][n][1];
            float v10 = alpha * acc[m][n][2], v11 = alpha * acc[m][n][3];
            if (OMODE == 0) {
                *reinterpret_cast<float2*>(&C[coff + (long)row * ldc + col]) = make_float2(v00, v01);
                *reinterpret_cast<float2*>(&C[coff + (long)(row + 8) * ldc + col]) = make_float2(v10, v11);
            } else if (OMODE == 1) {
                // tf32-rounded + k-permuted Q
                int c0 = permc(col), c1 = permc(col + 1);
                C[coff + (long)row * ldc + c0] = to_tf32_f(v00);
                C[coff + (long)row * ldc + c1] = to_tf32_f(v01);
                C[coff + (long)(row + 8) * ldc + c0] = to_tf32_f(v10);
                C[coff + (long)(row + 8) * ldc + c1] = to_tf32_f(v11);
            } else {
                if (col < NE) {   // K half: tf32 + permuted
                    int c0 = permc(col), c1 = permc(col + 1);
                    C[(long)row * NE + c0] = to_tf32_f(v00);
                    C[(long)row * NE + c1] = to_tf32_f(v01);
                    C[(long)(row + 8) * NE + c0] = to_tf32_f(v10);
                    C[(long)(row + 8) * NE + c1] = to_tf32_f(v11);
                } else {          // V half: tf32, plain layout
                    *reinterpret_cast<float2*>(&C2[(long)row * NE + col - NE]) =
                        make_float2(to_tf32_f(v00), to_tf32_f(v01));
                    *reinterpret_cast<float2*>(&C2[(long)(row + 8) * NE + col - NE]) =
                        make_float2(to_tf32_f(v10), to_tf32_f(v11));
                }
            }
        }
    }
}

// ---------------- block reductions ----------------
__device__ __forceinline__ float blockReduceMax(float v, float* red) {
    #pragma unroll
    for (int o = 16; o > 0; o >>= 1) v = fmaxf(v, __shfl_xor_sync(0xFFFFFFFFu, v, o));
    int w = threadIdx.x >> 5, lane = threadIdx.x & 31;
    __syncthreads();
    if (lane == 0) red[w] = v;
    __syncthreads();
    v = (lane < (blockDim.x >> 5)) ? red[lane] : -F32_INF;
    #pragma unroll
    for (int o = 16; o > 0; o >>= 1) v = fmaxf(v, __shfl_xor_sync(0xFFFFFFFFu, v, o));
    return v;
}
__device__ __forceinline__ float blockReduceMin(float v, float* red) {
    #pragma unroll
    for (int o = 16; o > 0; o >>= 1) v = fminf(v, __shfl_xor_sync(0xFFFFFFFFu, v, o));
    int w = threadIdx.x >> 5, lane = threadIdx.x & 31;
    __syncthreads();
    if (lane == 0) red[w] = v;
    __syncthreads();
    v = (lane < (blockDim.x >> 5)) ? red[lane] : F32_INF;
    #pragma unroll
    for (int o = 16; o > 0; o >>= 1) v = fminf(v, __shfl_xor_sync(0xFFFFFFFFu, v, o));
    return v;
}
__device__ __forceinline__ float blockReduceSum(float v, float* red) {
    #pragma unroll
    for (int o = 16; o > 0; o >>= 1) v += __shfl_xor_sync(0xFFFFFFFFu, v, o);
    int w = threadIdx.x >> 5, lane = threadIdx.x & 31;
    __syncthreads();
    if (lane == 0) red[w] = v;
    __syncthreads();
    v = (lane < (blockDim.x >> 5)) ? red[lane] : 0.f;
    #pragma unroll
    for (int o = 16; o > 0; o >>= 1) v += __shfl_xor_sync(0xFFFFFFFFu, v, o);
    return v;
}

// ---------------- softmax + differential + min-shift (float4 I/O) ----------------
__global__ __launch_bounds__(256) void softmax_diff_kernel(
    const void* __restrict__ qmask, const void* __restrict__ kmask,
    float* __restrict__ out_diff) {
    __shared__ float p1[NL];
    __shared__ float p2[NL];
    __shared__ float red[32];

    int bs = blockIdx.x;
    int b = bs >> 9;
    int s = bs & 511;
    int tid = threadIdx.x;
    int mode = g_mask_mode;

    bool qm = mask_at(qmask, bs, mode);
    const float* s1 = g_S + ((long)(b * 2 + 0) * NS + s) * NL;
    const float* s2 = g_S + ((long)(b * 2 + 1) * NS + s) * NL;
    long kmbase = (long)b * NL;

    float m1 = -F32_INF, m2 = -F32_INF;
    for (int l0 = tid * 4; l0 < NL; l0 += 1024) {
        float4 a = *reinterpret_cast<const float4*>(s1 + l0);
        float4 c = *reinterpret_cast<const float4*>(s2 + l0);
        float va[4] = {a.x, a.y, a.z, a.w};
        float vc[4] = {c.x, c.y, c.z, c.w};
        #pragma unroll
        for (int j = 0; j < 4; j++) {
            bool mk = qm && mask_at(kmask, kmbase + l0 + j, mode);
            va[j] = mk ? va[j] : -1e20f;
            vc[j] = mk ? vc[j] : -1e20f;
            m1 = fmaxf(m1, va[j]); m2 = fmaxf(m2, vc[j]);
        }
        *reinterpret_cast<float4*>(p1 + l0) = make_float4(va[0], va[1], va[2], va[3]);
        *reinterpret_cast<float4*>(p2 + l0) = make_float4(vc[0], vc[1], vc[2], vc[3]);
    }
    m1 = blockReduceMax(m1, red);
    m2 = blockReduceMax(m2, red);

    float sum1 = 0.f, sum2 = 0.f;
    for (int l = tid; l < NL; l += 256) {
        float e1 = expf(p1[l] - m1);
        float e2 = expf(p2[l] - m2);
        p1[l] = e1; p2[l] = e2;
        sum1 += e1; sum2 += e2;
    }
    sum1 = blockReduceSum(sum1, red);
    sum2 = blockReduceSum(sum2, red);
    float inv1 = 1.f / (sum1 + 1e-8f);
    float inv2 = 1.f / (sum2 + 1e-8f);
    float lam = g_lambda;

    float mn = F32_INF;
    for (int l = tid; l < NL; l += 256) {
        float d = p1[l] * inv1 - lam * (p2[l] * inv2);
        p1[l] = d;
        mn = fminf(mn, d);
    }
    mn = blockReduceMin(mn, red);

    float* od = out_diff + (long)bs * NL;
    for (int l0 = tid * 4; l0 < NL; l0 += 1024) {
        float v[4];
        #pragma unroll
        for (int j = 0; j < 4; j++) {
            bool mk = qm && mask_at(kmask, kmbase + l0 + j, mode);
            v[j] = mk ? (p1[l0 + j] - mn + 1e-20f) : 0.f;
        }
        *reinterpret_cast<float4*>(od + l0) = make_float4(v[0], v[1], v[2], v[3]);
    }
}

// ---------------- split-K reduce + RMS norm (fused), writes tf32 + k-permuted X ----------------
__global__ __launch_bounds__(256) void rmsnorm_kernel(const float* __restrict__ ln) {
    __shared__ float red[32];
    __shared__ float row_buf[NE];
    int row = blockIdx.x;
    int tid = threadIdx.x;
    const long rbase = (long)row * NE;
    const long pstride = (long)NB * NS * NE;
    float ss = 0.f;
    for (int e = tid; e < NE; e += 256) {
        float v = g_P[rbase + e] + g_P[pstride + rbase + e]
                + g_P[2 * pstride + rbase + e] + g_P[3 * pstride + rbase + e];
        row_buf[e] = v;
        ss += v * v;
    }
    ss = blockReduceSum(ss, red);
    float scale = rsqrtf(ss / (float)NE + 1e-5f) * (1.0f - LAMBDA_INIT);
    float* x = g_X + rbase;
    for (int e = tid; e < NE; e += 256)
        x[permc(e)] = to_tf32_f(row_buf[e] * scale * ln[e]);
}

// ---------------- launch ----------------
extern "C" void kernel_launch(void* const* d_in, const int* in_sizes, int n_in,
                              void* d_out, int out_size) {
    const float* query = (const float*)d_in[0];   // (8,512,768)
    const float* key   = (const float*)d_in[1];   // (8,64,64,32)
    const void*  qmask = d_in[2];                 // (8,512)
    const void*  kmask = d_in[3];                 // (8,64,64)
    const float* Wq   = (const float*)d_in[4];
    const float* Wkv  = (const float*)d_in[5];
    const float* Wout = (const float*)d_in[6];
    const float* lq1  = (const float*)d_in[7];
    const float* lk1  = (const float*)d_in[8];
    const float* lq2  = (const float*)d_in[9];
    const float* lk2  = (const float*)d_in[10];
    const float* ln   = (const float*)d_in[11];

    float* outp = (float*)d_out;                       // (8,512,768)
    float* diffp = outp + (long)NB * NS * NE;          // (8,512,64,64)

    float *pQI, *pKI, *pW1, *pW2, *pW3, *pQ, *pK, *pV, *pS, *pP, *pX;
    cudaGetSymbolAddress((void**)&pQI, g_QI);
    cudaGetSymbolAddress((void**)&pKI, g_KI);
    cudaGetSymbolAddress((void**)&pW1, g_W1);
    cudaGetSymbolAddress((void**)&pW2, g_W2);
    cudaGetSymbolAddress((void**)&pW3, g_W3);
    cudaGetSymbolAddress((void**)&pQ,  g_Q);
    cudaGetSymbolAddress((void**)&pK,  g_K);
    cudaGetSymbolAddress((void**)&pV,  g_V);
    cudaGetSymbolAddress((void**)&pS,  g_S);
    cudaGetSymbolAddress((void**)&pP,  g_P);
    cudaGetSymbolAddress((void**)&pX,  g_X);

    detect_mask_kernel<<<1, 256>>>((const unsigned char*)kmask);
    lambda_kernel<<<1, 384>>>(lq1, lk1, lq2, lk2);

    // fused pre-round: query(perm), key(perm), Wq, Wkv, Wout
    {
        RoundArgs ra;
        int n4[5] = { NB * NS * NE / 4, NB * NL * NGE / 4,
                      NE * NE / 4, NGE * 2 * NE / 4, NE * NE / 4 };
        ra.src[0] = query; ra.dst[0] = pQI; ra.perm[0] = 1;
        ra.src[1] = key;   ra.dst[1] = pKI; ra.perm[1] = 1;
        ra.src[2] = Wq;    ra.dst[2] = pW1; ra.perm[2] = 0;
        ra.src[3] = Wkv;   ra.dst[3] = pW2; ra.perm[3] = 0;
        ra.src[4] = Wout;  ra.dst[4] = pW3; ra.perm[4] = 0;
        int acc = 0;
        for (int i = 0; i < 5; i++) { acc += n4[i]; ra.end4[i] = acc; }
        round_all_kernel<<<(acc + 255) / 256, 256>>>(ra);
    }

    // Q = queryR @ WqR -> tf32 + permuted : M=4096, N=768, K=768
    mma_gemm<false, 1, false, true><<<dim3(NE / 128, (NB * NS) / 128, 1), 256>>>(
        pQI, pW1, pQ, nullptr, NB * NS, NE, NE, NE, NE, NE, 1.0f,
        1, 0, 0, 0, 0, 0, 0);

    // KV = keyR @ WkvR -> K(permuted) | V : M=32768, N=1536, K=32
    mma_gemm<false, 2, false, true><<<dim3((2 * NE) / 128, (NB * NL) / 128, 1), 256>>>(
        pKI, pW2, pK, pV, NB * NL, 2 * NE, NGE, NGE, 2 * NE, NE, 1.0f,
        1, 0, 0, 0, 0, 0, 0);

    // scores = SCALING * Qh @ Kh^T (both permuted) : M=512, N=4096, K=384, 16 batches
    mma_gemm<true, 0, false, true><<<dim3(NL / 128, NS / 128, NB * 2), 256>>>(
        pQ, pK, pS, nullptr, NS, NL, NHD, NE, NE, NL, SCALING,
        2,
        (long)NS * NE, (long)NHD,
        (long)NL * NE, (long)NHD,
        (long)2 * NS * NL, (long)NS * NL);

    // softmax + diff + min-shift -> d_out diff region
    softmax_diff_kernel<<<NB * NS, 256>>>(qmask, kmask, diffp);

    // attn_out partials: A=diff (exact fp32, cvt in-loop), B=V
    mma_gemm<false, 0, true, false><<<dim3(NE / 128, NS / 128, NB * KSPLIT), 256>>>(
        diffp, pV, pP, nullptr, NS, NE, NL / KSPLIT, NL, NE, NE, 1.0f,
        KSPLIT,
        (long)NS * NL, (long)(NL / KSPLIT),
        (long)NL * NE, (long)(NL / KSPLIT) * NE,
        (long)NS * NE, (long)NB * NS * NE);

    // split-K reduce + RMS norm (writes tf32 + permuted X)
    rmsnorm_kernel<<<NB * NS, 256>>>(ln);

    // out = XR @ WoutR : M=4096, N=768, K=768
    mma_gemm<false, 0, false, true><<<dim3(NE / 128, (NB * NS) / 128, 1), 256>>>(
        pX, pW3, outp, nullptr, NB * NS, NE, NE, NE, NE, NE, 1.0f,
        1, 0, 0, 0, 0, 0, 0);
}

// round 17
// speedup vs baseline: 1.1146x; 1.0428x over previous
#include <cuda_runtime.h>
#include <math.h>
#include <stdint.h>

#define F32_INF __int_as_float(0x7f800000)

// ---------------- problem constants ----------------
#define NB 8
#define NS 512
#define NE 768
#define NGE 32
#define NHD 384
#define NL 4096
#define LAMBDA_INIT 0.2f
#define SCALING 0.05103103630798287f   // 384^-0.5
#define KSPLIT 4

// k-group permutation: within each 8-col group, col c -> (c&3)*2 + (c>>2)
__host__ __device__ __forceinline__ int permc(int c) {
    return (c & ~7) | ((c & 3) << 1) | ((c >> 2) & 1);
}

// ---------------- scratch ----------------
__device__ float g_QI[NB * NS * NE];                    // tf32-rounded, k-permuted query
__device__ float g_KI[NB * NL * NGE];                   // tf32-rounded, k-permuted key
__device__ float g_W1[NE * NE];                         // tf32-rounded Wq
__device__ float g_W2[NGE * 2 * NE];                    // tf32-rounded Wkv
__device__ float g_W3[NE * NE];                         // tf32-rounded Wout
__device__ float g_Q[NB * NS * NE];                     // Q (tf32, k-permuted)
__device__ float g_K[(size_t)NB * NL * NE];             // K (tf32, k-permuted, ld 768)
__device__ float g_V[(size_t)NB * NL * NE];             // V (tf32, ld 768)
__device__ float g_S[(size_t)NB * 2 * NS * NL];         // raw scores
__device__ float g_P[(size_t)KSPLIT * NB * NS * NE];    // split-K partials for AV
__device__ float g_X[NB * NS * NE];                     // normed (tf32, k-permuted)
__device__ float g_lambda;
__device__ int   g_mask_mode;   // 0=uint8, 1=int32, 2=float32

// ---------------- cp.async helpers ----------------
__device__ __forceinline__ uint32_t smem_u32(const void* p) {
    return (uint32_t)__cvta_generic_to_shared(p);
}
#define CP_ASYNC16(dst, src) \
    asm volatile("cp.async.cg.shared.global [%0], [%1], 16;\n" :: "r"(dst), "l"(src))
#define CP_COMMIT() asm volatile("cp.async.commit_group;\n" ::)
#define CP_WAIT(N)  asm volatile("cp.async.wait_group %0;\n" :: "n"(N))

// ---------------- tf32 helpers ----------------
__device__ __forceinline__ uint32_t to_tf32_u(float x) {
    uint32_t r;
    asm("cvt.rna.tf32.f32 %0, %1;" : "=r"(r) : "f"(x));
    return r;
}
__device__ __forceinline__ float to_tf32_f(float x) {
    return __uint_as_float(to_tf32_u(x));
}
__device__ __forceinline__ void mma_tf32(float* d, const uint32_t* a, const uint32_t* b) {
    asm volatile(
        "mma.sync.aligned.m16n8k8.row.col.f32.tf32.tf32.f32 "
        "{%0,%1,%2,%3}, {%4,%5,%6,%7}, {%8,%9}, {%0,%1,%2,%3};"
        : "+f"(d[0]), "+f"(d[1]), "+f"(d[2]), "+f"(d[3])
        : "r"(a[0]), "r"(a[1]), "r"(a[2]), "r"(a[3]), "r"(b[0]), "r"(b[1]));
}

// ---------------- fused pre-round (5 segments, optional k-permute) ----------------
struct RoundArgs {
    const float* src[5];
    float* dst[5];
    int end4[5];
    int perm[5];
};
__global__ void round_all_kernel(RoundArgs a) {
    int i = blockIdx.x * blockDim.x + threadIdx.x;
    if (i >= a.end4[4]) return;
    int seg = 0;
    while (i >= a.end4[seg]) seg++;
    int j = i - (seg ? a.end4[seg - 1] : 0);
    float4 v = reinterpret_cast<const float4*>(a.src[seg])[j];
    v.x = to_tf32_f(v.x); v.y = to_tf32_f(v.y);
    v.z = to_tf32_f(v.z); v.w = to_tf32_f(v.w);
    if (a.perm[seg]) {
        float* d = a.dst[seg];
        int c = j * 4;
        d[permc(c)]     = v.x;
        d[permc(c + 1)] = v.y;
        d[permc(c + 2)] = v.z;
        d[permc(c + 3)] = v.w;
    } else {
        reinterpret_cast<float4*>(a.dst[seg])[j] = v;
    }
}

// ---------------- mask dtype detection ----------------
__global__ void detect_mask_kernel(const unsigned char* __restrict__ km) {
    __shared__ int s_non01, s_nonmult4;
    if (threadIdx.x == 0) { s_non01 = 0; s_nonmult4 = 0; }
    __syncthreads();
    int non01 = 0, nm4 = 0;
    for (int i = threadIdx.x; i < 32768; i += 256) {
        unsigned char v = km[i];
        if (v > 1) non01 = 1;
        if (v != 0 && (i & 3) != 0) nm4 = 1;
    }
    if (non01) atomicOr(&s_non01, 1);
    if (nm4)   atomicOr(&s_nonmult4, 1);
    __syncthreads();
    if (threadIdx.x == 0)
        g_mask_mode = s_non01 ? 2 : (s_nonmult4 ? 0 : 1);
}

__device__ __forceinline__ bool mask_at(const void* p, long idx, int mode) {
    if (mode == 1) return ((const int*)p)[idx] != 0;
    if (mode == 2) return ((const float*)p)[idx] != 0.0f;
    return ((const unsigned char*)p)[idx] != 0;
}

// ---------------- lambda scalar ----------------
__global__ void lambda_kernel(const float* __restrict__ lq1, const float* __restrict__ lk1,
                              const float* __restrict__ lq2, const float* __restrict__ lk2) {
    __shared__ float red1[12], red2[12];
    int t = threadIdx.x;
    float a = lq1[t] * lk1[t];
    float b = lq2[t] * lk2[t];
    #pragma unroll
    for (int o = 16; o > 0; o >>= 1) {
        a += __shfl_xor_sync(0xFFFFFFFFu, a, o);
        b += __shfl_xor_sync(0xFFFFFFFFu, b, o);
    }
    if ((t & 31) == 0) { red1[t >> 5] = a; red2[t >> 5] = b; }
    __syncthreads();
    if (t == 0) {
        float s1 = 0.f, s2 = 0.f;
        for (int i = 0; i < 12; i++) { s1 += red1[i]; s2 += red2[i]; }
        g_lambda = expf(s1) - expf(s2) + LAMBDA_INIT;
    }
}

// ---------------- GEMM core (device function; dynamic smem passed in) ----------------
// C[m0:,n0:] tile of: alpha * A[.,K] @ (TB ? B[N,K]^T : B[K,N])
// PERM: A (and B if TB) k-permuted -> float2 fragment loads, pitch 24; else pitch 20.
// CVTA: round A in-loop. OMODE 0: raw fp32 C. 1: tf32+permuted C. 2: KV split.
template <bool TB, int OMODE, bool CVTA, bool PERM>
__device__ __forceinline__ void gemm_core(
    float* sm,
    const float* A, const float* B, float* C, float* C2,
    int m0, int n0, int K, int lda, int ldb, int ldc, float alpha, long coff) {
    const int BM = 128, BN = 128, BK = 16;
    const int APITCH = PERM ? (BK + 8) : (BK + 4);       // 24 : 20
    const int BPITCH_NT = PERM ? (BK + 8) : (BK + 4);
    const int BPITCH_NN = BN + 8;                        // 136
    float* As = sm;                                      // 3 stages
    float* Bs = sm + 3 * BM * APITCH;

    int tid = threadIdx.x;
    int warp = tid >> 5, lane = tid & 31;
    int g = lane >> 2, tg = lane & 3;
    int wm = (warp & 3) * 32, wn = (warp >> 2) * 64;

    int ar[2], ac[2], br[2], bc[2];
    #pragma unroll
    for (int rep = 0; rep < 2; rep++) {
        int idx = rep * 256 + tid;
        ar[rep] = idx >> 2; ac[rep] = (idx & 3) * 4;
        if (TB) { br[rep] = idx >> 2; bc[rep] = (idx & 3) * 4; }
        else    { br[rep] = idx >> 5; bc[rep] = (idx & 31) * 4; }
    }

    int niter = K / BK;
    const int ASTG = BM * APITCH;
    const int BSTG = TB ? BN * BPITCH_NT : BK * BPITCH_NN;

    auto prefetch = [&](int st, int buf) {
        int k0 = st * BK;
        #pragma unroll
        for (int rep = 0; rep < 2; rep++) {
            CP_ASYNC16(smem_u32(&As[buf * ASTG + ar[rep] * APITCH + ac[rep]]),
                       &A[(long)(m0 + ar[rep]) * lda + k0 + ac[rep]]);
            if (TB)
                CP_ASYNC16(smem_u32(&Bs[buf * BSTG + br[rep] * BPITCH_NT + bc[rep]]),
                           &B[(long)(n0 + br[rep]) * ldb + k0 + bc[rep]]);
            else
                CP_ASYNC16(smem_u32(&Bs[buf * BSTG + br[rep] * BPITCH_NN + bc[rep]]),
                           &B[(long)(k0 + br[rep]) * ldb + n0 + bc[rep]]);
        }
    };

    prefetch(0, 0); CP_COMMIT();
    prefetch(1, 1); CP_COMMIT();

    float acc[2][8][4] = {};

    for (int it = 0; it < niter; it++) {
        int cur = it % 3;
        CP_WAIT(1);
        __syncthreads();

        if (it + 2 < niter) prefetch(it + 2, (it + 2) % 3);
        CP_COMMIT();

        const float* Asc = As + cur * ASTG;
        const float* Bsc = Bs + cur * BSTG;
        #pragma unroll
        for (int kk = 0; kk < BK; kk += 8) {
            uint32_t af[2][4], bf[8][2];
            #pragma unroll
            for (int m = 0; m < 2; m++) {
                int row = wm + m * 16;
                if (PERM) {
                    float2 v0 = *reinterpret_cast<const float2*>(&Asc[(row + g)     * APITCH + kk + 2 * tg]);
                    float2 v1 = *reinterpret_cast<const float2*>(&Asc[(row + g + 8) * APITCH + kk + 2 * tg]);
                    af[m][0] = __float_as_uint(v0.x); af[m][2] = __float_as_uint(v0.y);
                    af[m][1] = __float_as_uint(v1.x); af[m][3] = __float_as_uint(v1.y);
                } else if (CVTA) {
                    af[m][0] = to_tf32_u(Asc[(row + g)     * APITCH + kk + tg]);
                    af[m][1] = to_tf32_u(Asc[(row + g + 8) * APITCH + kk + tg]);
                    af[m][2] = to_tf32_u(Asc[(row + g)     * APITCH + kk + tg + 4]);
                    af[m][3] = to_tf32_u(Asc[(row + g + 8) * APITCH + kk + tg + 4]);
                } else {
                    af[m][0] = __float_as_uint(Asc[(row + g)     * APITCH + kk + tg]);
                    af[m][1] = __float_as_uint(Asc[(row + g + 8) * APITCH + kk + tg]);
                    af[m][2] = __float_as_uint(Asc[(row + g)     * APITCH + kk + tg + 4]);
                    af[m][3] = __float_as_uint(Asc[(row + g + 8) * APITCH + kk + tg + 4]);
                }
            }
            #pragma unroll
            for (int n = 0; n < 8; n++) {
                int col = wn + n * 8 + g;
                if (TB) {
                    if (PERM) {
                        float2 v = *reinterpret_cast<const float2*>(&Bsc[col * BPITCH_NT + kk + 2 * tg]);
                        bf[n][0] = __float_as_uint(v.x); bf[n][1] = __float_as_uint(v.y);
                    } else {
                        bf[n][0] = __float_as_uint(Bsc[col * BPITCH_NT + kk + tg]);
                        bf[n][1] = __float_as_uint(Bsc[col * BPITCH_NT + kk + tg + 4]);
                    }
                } else {
                    bf[n][0] = __float_as_uint(Bsc[(kk + tg)     * BPITCH_NN + col]);
                    bf[n][1] = __float_as_uint(Bsc[(kk + tg + 4) * BPITCH_NN + col]);
                }
            }
            #pragma unroll
            for (int m = 0; m < 2; m++)
                #pragma unroll
                for (int n = 0; n < 8; n++)
                    mma_tf32(acc[m][n], af[m], bf[n]);
        }
    }

    // ---- epilogue ----
    #pragma unroll
    for (int m = 0; m < 2; m++) {
        #pragma unroll
        for (int n = 0; n < 8; n++) {
            int row = m0 + wm + m * 16 + g;
            int col = n0 + wn + n * 8 + tg * 2;
            float v00 = alpha * acc[m][n][0], v01 = alpha * acc[m][n][1];
            float v10 = alpha * acc[m][n][2], v11 = alpha * acc[m][n][3];
            if (OMODE == 0) {
                *reinterpret_cast<float2*>(&C[coff + (long)row * ldc + col]) = make_float2(v00, v01);
                *reinterpret_cast<float2*>(&C[coff + (long)(row + 8) * ldc + col]) = make_float2(v10, v11);
            } else if (OMODE == 1) {
                int c0 = permc(col), c1 = permc(col + 1);
                C[coff + (long)row * ldc + c0] = to_tf32_f(v00);
                C[coff + (long)row * ldc + c1] = to_tf32_f(v01);
                C[coff + (long)(row + 8) * ldc + c0] = to_tf32_f(v10);
                C[coff + (long)(row + 8) * ldc + c1] = to_tf32_f(v11);
            } else {
                if (col < NE) {   // K half: tf32 + permuted
                    int c0 = permc(col), c1 = permc(col + 1);
                    C[(long)row * NE + c0] = to_tf32_f(v00);
                    C[(long)row * NE + c1] = to_tf32_f(v01);
                    C[(long)(row + 8) * NE + c0] = to_tf32_f(v10);
                    C[(long)(row + 8) * NE + c1] = to_tf32_f(v11);
                } else {          // V half: tf32, plain layout
                    *reinterpret_cast<float2*>(&C2[(long)row * NE + col - NE]) =
                        make_float2(to_tf32_f(v00), to_tf32_f(v01));
                    *reinterpret_cast<float2*>(&C2[(long)(row + 8) * NE + col - NE]) =
                        make_float2(to_tf32_f(v10), to_tf32_f(v11));
                }
            }
        }
    }
}

// ---------------- generic batched GEMM wrapper ----------------
template <bool TB, int OMODE, bool CVTA, bool PERM>
__global__ __launch_bounds__(256) void mma_gemm(
    const float* __restrict__ A, const float* __restrict__ B,
    float* __restrict__ C, float* __restrict__ C2,
    int K, int lda, int ldb, int ldc, float alpha, int dv,
    long sAhi, long sAlo, long sBhi, long sBlo, long sChi, long sClo) {
    extern __shared__ float dynsm[];
    int z = blockIdx.z;
    const float* Az = A + (long)(z / dv) * sAhi + (long)(z % dv) * sAlo;
    const float* Bz = B + (long)(z / dv) * sBhi + (long)(z % dv) * sBlo;
    long coff = (long)(z / dv) * sChi + (long)(z % dv) * sClo;
    gemm_core<TB, OMODE, CVTA, PERM>(dynsm, Az, Bz, C, C2,
                                     blockIdx.y * 128, blockIdx.x * 128,
                                     K, lda, ldb, ldc, alpha, coff);
}

// ---------------- fused Q-proj + KV-proj (independent ops, one launch) ----------------
// ids [0,192): Q = QI @ W1 -> g_Q (OMODE1), tiles 6 x 32
// ids [192, 3264): KV = KI @ W2 -> g_K | g_V (OMODE2), tiles 12 x 256
#define QKV_NQ 192
#define QKV_TOTAL (QKV_NQ + 3072)
__global__ __launch_bounds__(256) void qkv_fused_kernel() {
    extern __shared__ float dynsm[];
    int id = blockIdx.x;
    if (id < QKV_NQ) {
        int bx = id % 6, by = id / 6;
        gemm_core<false, 1, false, true>(dynsm, g_QI, g_W1, g_Q, nullptr,
                                         by * 128, bx * 128, NE, NE, NE, NE, 1.0f, 0);
    } else {
        int id2 = id - QKV_NQ;
        int bx = id2 % 12, by = id2 / 12;
        gemm_core<false, 2, false, true>(dynsm, g_KI, g_W2, g_K, g_V,
                                         by * 128, bx * 128, NGE, NGE, 2 * NE, NE, 1.0f, 0);
    }
}

// ---------------- block reductions ----------------
__device__ __forceinline__ float blockReduceMax(float v, float* red) {
    #pragma unroll
    for (int o = 16; o > 0; o >>= 1) v = fmaxf(v, __shfl_xor_sync(0xFFFFFFFFu, v, o));
    int w = threadIdx.x >> 5, lane = threadIdx.x & 31;
    __syncthreads();
    if (lane == 0) red[w] = v;
    __syncthreads();
    v = (lane < (blockDim.x >> 5)) ? red[lane] : -F32_INF;
    #pragma unroll
    for (int o = 16; o > 0; o >>= 1) v = fmaxf(v, __shfl_xor_sync(0xFFFFFFFFu, v, o));
    return v;
}
__device__ __forceinline__ float blockReduceMin(float v, float* red) {
    #pragma unroll
    for (int o = 16; o > 0; o >>= 1) v = fminf(v, __shfl_xor_sync(0xFFFFFFFFu, v, o));
    int w = threadIdx.x >> 5, lane = threadIdx.x & 31;
    __syncthreads();
    if (lane == 0) red[w] = v;
    __syncthreads();
    v = (lane < (blockDim.x >> 5)) ? red[lane] : F32_INF;
    #pragma unroll
    for (int o = 16; o > 0; o >>= 1) v = fminf(v, __shfl_xor_sync(0xFFFFFFFFu, v, o));
    return v;
}
__device__ __forceinline__ float blockReduceSum(float v, float* red) {
    #pragma unroll
    for (int o = 16; o > 0; o >>= 1) v += __shfl_xor_sync(0xFFFFFFFFu, v, o);
    int w = threadIdx.x >> 5, lane = threadIdx.x & 31;
    __syncthreads();
    if (lane == 0) red[w] = v;
    __syncthreads();
    v = (lane < (blockDim.x >> 5)) ? red[lane] : 0.f;
    #pragma unroll
    for (int o = 16; o > 0; o >>= 1) v += __shfl_xor_sync(0xFFFFFFFFu, v, o);
    return v;
}

// ---------------- softmax + differential + min-shift (float4 I/O) ----------------
__global__ __launch_bounds__(256) void softmax_diff_kernel(
    const void* __restrict__ qmask, const void* __restrict__ kmask,
    float* __restrict__ out_diff) {
    __shared__ float p1[NL];
    __shared__ float p2[NL];
    __shared__ float red[32];

    int bs = blockIdx.x;
    int b = bs >> 9;
    int s = bs & 511;
    int tid = threadIdx.x;
    int mode = g_mask_mode;

    bool qm = mask_at(qmask, bs, mode);
    const float* s1 = g_S + ((long)(b * 2 + 0) * NS + s) * NL;
    const float* s2 = g_S + ((long)(b * 2 + 1) * NS + s) * NL;
    long kmbase = (long)b * NL;

    float m1 = -F32_INF, m2 = -F32_INF;
    for (int l0 = tid * 4; l0 < NL; l0 += 1024) {
        float4 a = *reinterpret_cast<const float4*>(s1 + l0);
        float4 c = *reinterpret_cast<const float4*>(s2 + l0);
        float va[4] = {a.x, a.y, a.z, a.w};
        float vc[4] = {c.x, c.y, c.z, c.w};
        #pragma unroll
        for (int j = 0; j < 4; j++) {
            bool mk = qm && mask_at(kmask, kmbase + l0 + j, mode);
            va[j] = mk ? va[j] : -1e20f;
            vc[j] = mk ? vc[j] : -1e20f;
            m1 = fmaxf(m1, va[j]); m2 = fmaxf(m2, vc[j]);
        }
        *reinterpret_cast<float4*>(p1 + l0) = make_float4(va[0], va[1], va[2], va[3]);
        *reinterpret_cast<float4*>(p2 + l0) = make_float4(vc[0], vc[1], vc[2], vc[3]);
    }
    m1 = blockReduceMax(m1, red);
    m2 = blockReduceMax(m2, red);

    float sum1 = 0.f, sum2 = 0.f;
    for (int l = tid; l < NL; l += 256) {
        float e1 = expf(p1[l] - m1);
        float e2 = expf(p2[l] - m2);
        p1[l] = e1; p2[l] = e2;
        sum1 += e1; sum2 += e2;
    }
    sum1 = blockReduceSum(sum1, red);
    sum2 = blockReduceSum(sum2, red);
    float inv1 = 1.f / (sum1 + 1e-8f);
    float inv2 = 1.f / (sum2 + 1e-8f);
    float lam = g_lambda;

    float mn = F32_INF;
    for (int l = tid; l < NL; l += 256) {
        float d = p1[l] * inv1 - lam * (p2[l] * inv2);
        p1[l] = d;
        mn = fminf(mn, d);
    }
    mn = blockReduceMin(mn, red);

    float* od = out_diff + (long)bs * NL;
    for (int l0 = tid * 4; l0 < NL; l0 += 1024) {
        float v[4];
        #pragma unroll
        for (int j = 0; j < 4; j++) {
            bool mk = qm && mask_at(kmask, kmbase + l0 + j, mode);
            v[j] = mk ? (p1[l0 + j] - mn + 1e-20f) : 0.f;
        }
        *reinterpret_cast<float4*>(od + l0) = make_float4(v[0], v[1], v[2], v[3]);
    }
}

// ---------------- split-K reduce + RMS norm (fused), writes tf32 + k-permuted X ----------------
__global__ __launch_bounds__(256) void rmsnorm_kernel(const float* __restrict__ ln) {
    __shared__ float red[32];
    __shared__ float row_buf[NE];
    int row = blockIdx.x;
    int tid = threadIdx.x;
    const long rbase = (long)row * NE;
    const long pstride = (long)NB * NS * NE;
    float ss = 0.f;
    for (int e = tid; e < NE; e += 256) {
        float v = g_P[rbase + e] + g_P[pstride + rbase + e]
                + g_P[2 * pstride + rbase + e] + g_P[3 * pstride + rbase + e];
        row_buf[e] = v;
        ss += v * v;
    }
    ss = blockReduceSum(ss, red);
    float scale = rsqrtf(ss / (float)NE + 1e-5f) * (1.0f - LAMBDA_INIT);
    float* x = g_X + rbase;
    for (int e = tid; e < NE; e += 256)
        x[permc(e)] = to_tf32_f(row_buf[e] * scale * ln[e]);
}

// ---------------- dynamic smem sizes (bytes) ----------------
#define SM_NN_PERM   ((3 * 128 * 24 + 3 * 16 * 136) * 4)   // 62976  (fused, Wout)
#define SM_TB_PERM   ((3 * 128 * 24 + 3 * 128 * 24) * 4)   // 73728  (scores)
#define SM_NN_PLAIN  ((3 * 128 * 20 + 3 * 16 * 136) * 4)   // 56832  (AV)

// ---------------- launch ----------------
extern "C" void kernel_launch(void* const* d_in, const int* in_sizes, int n_in,
                              void* d_out, int out_size) {
    const float* query = (const float*)d_in[0];
    const float* key   = (const float*)d_in[1];
    const void*  qmask = d_in[2];
    const void*  kmask = d_in[3];
    const float* Wq   = (const float*)d_in[4];
    const float* Wkv  = (const float*)d_in[5];
    const float* Wout = (const float*)d_in[6];
    const float* lq1  = (const float*)d_in[7];
    const float* lk1  = (const float*)d_in[8];
    const float* lq2  = (const float*)d_in[9];
    const float* lk2  = (const float*)d_in[10];
    const float* ln   = (const float*)d_in[11];

    float* outp = (float*)d_out;
    float* diffp = outp + (long)NB * NS * NE;

    float *pQI, *pKI, *pW1, *pW2, *pW3, *pQ, *pK, *pV, *pS, *pP, *pX;
    cudaGetSymbolAddress((void**)&pQI, g_QI);
    cudaGetSymbolAddress((void**)&pKI, g_KI);
    cudaGetSymbolAddress((void**)&pW1, g_W1);
    cudaGetSymbolAddress((void**)&pW2, g_W2);
    cudaGetSymbolAddress((void**)&pW3, g_W3);
    cudaGetSymbolAddress((void**)&pQ,  g_Q);
    cudaGetSymbolAddress((void**)&pK,  g_K);
    cudaGetSymbolAddress((void**)&pV,  g_V);
    cudaGetSymbolAddress((void**)&pS,  g_S);
    cudaGetSymbolAddress((void**)&pP,  g_P);
    cudaGetSymbolAddress((void**)&pX,  g_X);

    // opt-in for >48KB dynamic smem (idempotent, host-side)
    cudaFuncSetAttribute(qkv_fused_kernel,
                         cudaFuncAttributeMaxDynamicSharedMemorySize, SM_NN_PERM);
    cudaFuncSetAttribute(mma_gemm<true, 0, false, true>,
                         cudaFuncAttributeMaxDynamicSharedMemorySize, SM_TB_PERM);
    cudaFuncSetAttribute(mma_gemm<false, 0, true, false>,
                         cudaFuncAttributeMaxDynamicSharedMemorySize, SM_NN_PLAIN);
    cudaFuncSetAttribute(mma_gemm<false, 0, false, true>,
                         cudaFuncAttributeMaxDynamicSharedMemorySize, SM_NN_PERM);

    detect_mask_kernel<<<1, 256>>>((const unsigned char*)kmask);
    lambda_kernel<<<1, 384>>>(lq1, lk1, lq2, lk2);

    // fused pre-round: query(perm), key(perm), Wq, Wkv, Wout
    {
        RoundArgs ra;
        int n4[5] = { NB * NS * NE / 4, NB * NL * NGE / 4,
                      NE * NE / 4, NGE * 2 * NE / 4, NE * NE / 4 };
        ra.src[0] = query; ra.dst[0] = pQI; ra.perm[0] = 1;
        ra.src[1] = key;   ra.dst[1] = pKI; ra.perm[1] = 1;
        ra.src[2] = Wq;    ra.dst[2] = pW1; ra.perm[2] = 0;
        ra.src[3] = Wkv;   ra.dst[3] = pW2; ra.perm[3] = 0;
        ra.src[4] = Wout;  ra.dst[4] = pW3; ra.perm[4] = 0;
        int acc = 0;
        for (int i = 0; i < 5; i++) { acc += n4[i]; ra.end4[i] = acc; }
        round_all_kernel<<<(acc + 255) / 256, 256>>>(ra);
    }

    // fused Q-proj + KV-proj (independent; one launch fills the machine)
    qkv_fused_kernel<<<QKV_TOTAL, 256, SM_NN_PERM>>>();

    // scores = SCALING * Qh @ Kh^T (both permuted) : M=512, N=4096, K=384, 16 batches
    mma_gemm<true, 0, false, true><<<dim3(NL / 128, NS / 128, NB * 2), 256, SM_TB_PERM>>>(
        pQ, pK, pS, nullptr, NHD, NE, NE, NL, SCALING,
        2,
        (long)NS * NE, (long)NHD,
        (long)NL * NE, (long)NHD,
        (long)2 * NS * NL, (long)NS * NL);

    // softmax + diff + min-shift -> d_out diff region
    softmax_diff_kernel<<<NB * NS, 256>>>(qmask, kmask, diffp);

    // attn_out partials: A=diff (exact fp32, cvt in-loop), B=V
    mma_gemm<false, 0, true, false><<<dim3(NE / 128, NS / 128, NB * KSPLIT), 256, SM_NN_PLAIN>>>(
        diffp, pV, pP, nullptr, NL / KSPLIT, NL, NE, NE, 1.0f,
        KSPLIT,
        (long)NS * NL, (long)(NL / KSPLIT),
        (long)NL * NE, (long)(NL / KSPLIT) * NE,
        (long)NS * NE, (long)NB * NS * NE);

    // split-K reduce + RMS norm (writes tf32 + permuted X)
    rmsnorm_kernel<<<NB * NS, 256>>>(ln);

    // out = XR @ WoutR : M=4096, N=768, K=768
    mma_gemm<false, 0, false, true><<<dim3(NE / 128, (NB * NS) / 128, 1), 256, SM_NN_PERM>>>(
        pX, pW3, outp, nullptr, NE, NE, NE, NE, 1.0f,
        1, 0, 0, 0, 0, 0, 0);
}